// round 12
// baseline (speedup 1.0000x reference)
#include <cuda_runtime.h>
#include <cstdint>

#define DIM 4096
#define THREADS 128   // 4 warps; each CTA does 2 rows, both loaded up front

// padded smem address for element e: +4 words per 128 elements
#define SADDR(e) ((e) + 4 * ((e) >> 7))

__device__ __forceinline__ void bfly(float& a, float& b) {
    float s = a + b;
    float d = a - b;
    a = s; b = d;
}

__device__ __forceinline__ uint64_t policy_evict_last() {
    uint64_t pol;
    asm("createpolicy.fractional.L2::evict_last.b64 %0, 1.0;" : "=l"(pol));
    return pol;
}
__device__ __forceinline__ uint64_t policy_evict_first() {
    uint64_t pol;
    asm("createpolicy.fractional.L2::evict_first.b64 %0, 1.0;" : "=l"(pol));
    return pol;
}
__device__ __forceinline__ float4 ldg_hint(const float4* p, uint64_t pol) {
    float4 f;
    asm volatile("ld.global.nc.L2::cache_hint.v4.f32 {%0,%1,%2,%3}, [%4], %5;"
                 : "=f"(f.x), "=f"(f.y), "=f"(f.z), "=f"(f.w)
                 : "l"(p), "l"(pol));
    return f;
}
__device__ __forceinline__ void stg_hint(float4* p, float4 f, uint64_t pol) {
    asm volatile("st.global.L2::cache_hint.v4.f32 [%0], {%1,%2,%3,%4}, %5;"
                 :: "l"(p), "f"(f.x), "f"(f.y), "f"(f.z), "f"(f.w), "l"(pol)
                 : "memory");
}

// ---- phase 1 butterfly: all 5 register bits (e-bits {0,1,9,10,11}) ----
__device__ __forceinline__ void p1_bfly(float* v) {
#pragma unroll
    for (int h = 1; h <= 16; h <<= 1) {
#pragma unroll
        for (int k = 0; k < 32; k++)
            if (!(k & h)) bfly(v[k], v[k ^ h]);
    }
}

// ---- store phase-1 registers to padded exchange buffer ----
__device__ __forceinline__ void p1_store(const float* v, float* s, int t) {
    const int base = 4 * t + 4 * (t >> 5);  // SADDR(4t + 512*kh) = base + 528*kh
#pragma unroll
    for (int kh = 0; kh < 8; kh++) {
        *reinterpret_cast<float4*>(&s[base + 528 * kh]) =
            make_float4(v[4 * kh + 0], v[4 * kh + 1],
                        v[4 * kh + 2], v[4 * kh + 3]);
    }
}

// ---- phases 2+3: smem exchange butterflies + global store of one row ----
// (contains one internal __syncthreads between P2 writeback and P3 reads)
__device__ __forceinline__ void p23(float* s, float4* oq, int t, uint64_t pol_st) {
    // Phase 2: e = k_lo2 + 4*j + 128*m ; reg bits j = e-bits {2..6}
    {
        float u[32];
        const int klo2 = t & 3;
        const int m = t >> 2;
        const int base2 = klo2 + 132 * m;  // SADDR(k_lo2 + 128*m); +4j exact
#pragma unroll
        for (int j = 0; j < 32; j++) u[j] = s[base2 + 4 * j];

#pragma unroll
        for (int h = 1; h <= 16; h <<= 1) {
#pragma unroll
            for (int j = 0; j < 32; j++)
                if (!(j & h)) bfly(u[j], u[j ^ h]);
        }
        // write back to SAME addresses (thread-private this phase)
#pragma unroll
        for (int j = 0; j < 32; j++) s[base2 + 4 * j] = u[j];
    }
    __syncthreads();

    // Phase 3: e = k_lo3 + 4*l + 128*km + 1024*w3 ;
    // reg bits = e-bits {0,1,7,8,9}, butterfly {7,8}
    {
        float w[32];
        const int l = t & 31;
        const int w3 = t >> 5;
        const int base3 = 4 * l + 1056 * w3;  // SADDR(4l + 1024*w3)
#pragma unroll
        for (int km = 0; km < 8; km++) {
            float4 f = *reinterpret_cast<const float4*>(&s[base3 + 132 * km]);
            w[4 * km + 0] = f.x;
            w[4 * km + 1] = f.y;
            w[4 * km + 2] = f.z;
            w[4 * km + 3] = f.w;
        }
#pragma unroll
        for (int h = 4; h <= 8; h <<= 1) {
#pragma unroll
            for (int k = 0; k < 32; k++)
                if (!(k & h)) bfly(w[k], w[k ^ h]);
        }
#pragma unroll
        for (int km = 0; km < 8; km++) {
            stg_hint(oq + l + 32 * km + 256 * w3,
                     make_float4(w[4 * km + 0], w[4 * km + 1],
                                 w[4 * km + 2], w[4 * km + 3]),
                     pol_st);
        }
    }
}

__global__ __launch_bounds__(THREADS, 6)   // 85 regs available; need ~80
void fwht4096_v12_kernel(const float* __restrict__ x, float* __restrict__ out) {
    __shared__ float s[DIM + 4 * (DIM >> 7)];  // 4224 floats = 16896 B

    const int t = threadIdx.x;
    const int row0 = 2 * blockIdx.x;

    const uint64_t pol_ld = policy_evict_last();
    const uint64_t pol_st = policy_evict_first();

    const float4* __restrict__ xa =
        reinterpret_cast<const float4*>(x + (size_t)row0 * DIM);
    const float4* __restrict__ xb = xa + (DIM / 4);
    float4* __restrict__ oa =
        reinterpret_cast<float4*>(out + (size_t)row0 * DIM);
    float4* __restrict__ ob = oa + (DIM / 4);

    // ---- front-batch BOTH rows' loads: 16 LDG.128 outstanding per thread ----
    float va[32], vb[32];
#pragma unroll
    for (int kh = 0; kh < 8; kh++) {
        float4 f = ldg_hint(xa + t + 128 * kh, pol_ld);
        va[4 * kh + 0] = f.x; va[4 * kh + 1] = f.y;
        va[4 * kh + 2] = f.z; va[4 * kh + 3] = f.w;
    }
#pragma unroll
    for (int kh = 0; kh < 8; kh++) {
        float4 f = ldg_hint(xb + t + 128 * kh, pol_ld);
        vb[4 * kh + 0] = f.x; vb[4 * kh + 1] = f.y;
        vb[4 * kh + 2] = f.z; vb[4 * kh + 3] = f.w;
    }

    // ---- row A through the pipeline ----
    p1_bfly(va);
    p1_store(va, s, t);
    __syncthreads();

    // row B's P1 butterflies overlap other warps' smem phase for row A
    p1_bfly(vb);

    p23(s, oa, t, pol_st);
    __syncthreads();   // all P3 reads of ex done before row B overwrites it

    // ---- row B through the pipeline ----
    p1_store(vb, s, t);
    __syncthreads();
    p23(s, ob, t, pol_st);
}

extern "C" void kernel_launch(void* const* d_in, const int* in_sizes, int n_in,
                              void* d_out, int out_size) {
    // x is the input whose element count equals out_size (N_TOKENS*DIM);
    // H is implicit in the transform and never read.
    const float* x = (const float*)d_in[0];
    for (int i = 0; i < n_in; i++) {
        if (in_sizes[i] == out_size) { x = (const float*)d_in[i]; break; }
    }
    float* out = (float*)d_out;
    const int n_rows = out_size / DIM;        // 8192
    fwht4096_v12_kernel<<<n_rows / 2, THREADS>>>(x, out);
}

// round 13
// speedup vs baseline: 1.0077x; 1.0077x over previous
#include <cuda_runtime.h>
#include <cstdint>

#define DIM 4096
#define THREADS 128   // one row per CTA, 4 warps

__device__ __forceinline__ uint64_t policy_evict_last() {
    uint64_t pol;
    asm("createpolicy.fractional.L2::evict_last.b64 %0, 1.0;" : "=l"(pol));
    return pol;
}
__device__ __forceinline__ uint64_t policy_evict_first() {
    uint64_t pol;
    asm("createpolicy.fractional.L2::evict_first.b64 %0, 1.0;" : "=l"(pol));
    return pol;
}
__device__ __forceinline__ float4 ldg_hint(const float4* p, uint64_t pol) {
    float4 f;
    asm volatile("ld.global.nc.L2::cache_hint.v4.f32 {%0,%1,%2,%3}, [%4], %5;"
                 : "=f"(f.x), "=f"(f.y), "=f"(f.z), "=f"(f.w)
                 : "l"(p), "l"(pol));
    return f;
}
__device__ __forceinline__ void stg_hint(float4* p, float4 f, uint64_t pol) {
    asm volatile("st.global.L2::cache_hint.v4.f32 [%0], {%1,%2,%3,%4}, %5;"
                 :: "l"(p), "f"(f.x), "f"(f.y), "f"(f.z), "f"(f.w), "l"(pol)
                 : "memory");
}

// packed butterfly on two float2s: (a,b) -> (a+b, a-b), elementwise on both
// lanes. 2 instructions for 2 butterflies (vs 4 scalar).
#define NEG1X2 0xBF800000BF800000ULL
__device__ __forceinline__ void bfly2(float2& a, float2& b) {
    uint64_t ua = *reinterpret_cast<uint64_t*>(&a);
    uint64_t ub = *reinterpret_cast<uint64_t*>(&b);
    uint64_t s, d;
    asm("add.rn.f32x2 %0, %1, %2;" : "=l"(s) : "l"(ua), "l"(ub));
    asm("fma.rn.f32x2 %0, %1, %2, %3;" : "=l"(d)
        : "l"(ub), "l"(NEG1X2), "l"(ua));   // a + (-1)*b
    *reinterpret_cast<uint64_t*>(&a) = s;
    *reinterpret_cast<uint64_t*>(&b) = d;
}
// intra-pair butterfly (stage h == reg-stride 1): scalar, unavoidable
__device__ __forceinline__ void bfly_in(float2& a) {
    float s = a.x + a.y;
    float d = a.x - a.y;
    a.x = s; a.y = d;
}
// run packed stages with pair-strides given by mask range [lo, hi]
__device__ __forceinline__ void packed_stages(float2* p, int lo, int hi) {
#pragma unroll
    for (int ph = lo; ph <= hi; ph <<= 1) {
#pragma unroll
        for (int i = 0; i < 16; i++)
            if (!(i & ph)) bfly2(p[i], p[i ^ ph]);
    }
}

__global__ __launch_bounds__(THREADS)
void fwht4096_v13_kernel(const float* __restrict__ x, float* __restrict__ out) {
    __shared__ float s[DIM + 4 * (DIM >> 7)];  // 4224 floats, padded layout

    const int row = blockIdx.x;
    const int t = threadIdx.x;

    const uint64_t pol_ld = policy_evict_last();
    const uint64_t pol_st = policy_evict_first();

    const float4* __restrict__ xin =
        reinterpret_cast<const float4*>(x + (size_t)row * DIM);
    float4* __restrict__ oq =
        reinterpret_cast<float4*>(out + (size_t)row * DIM);

    // ================= Phase 1 =================
    // element k = k_lo + 4*t + 512*k_hi ; reg k = 4*k_hi + k_lo
    // pair index p = k/2 ; pair lanes = e-bit 0 (intra-pair)
    float2 v[16];
#pragma unroll
    for (int kh = 0; kh < 8; kh++) {
        float4 f = ldg_hint(xin + t + 128 * kh, pol_ld);  // coalesced 512B/warp
        v[2 * kh + 0] = make_float2(f.x, f.y);
        v[2 * kh + 1] = make_float2(f.z, f.w);
    }

    // h=1 (e-bit 0): intra-pair scalar; h=2,4,8,16 -> pair strides 1,2,4,8
#pragma unroll
    for (int i = 0; i < 16; i++) bfly_in(v[i]);
    packed_stages(v, 1, 8);

    // store to padded exchange buffer (float4, conflict-free; same as R8)
    {
        const int base = 4 * t + 4 * (t >> 5);  // SADDR(4t+512kh) = base + 528kh
#pragma unroll
        for (int kh = 0; kh < 8; kh++) {
            *reinterpret_cast<float4*>(&s[base + 528 * kh]) =
                make_float4(v[2 * kh].x, v[2 * kh].y,
                            v[2 * kh + 1].x, v[2 * kh + 1].y);
        }
    }
    __syncthreads();

    // ================= Phase 2 =================
    // e = k_lo2 + 4*j + 128*m ; reg bits j = e-bits {2..6}
    // pair q = j/2 ; intra-pair = j-bit0 (e-bit 2)
    {
        float2 u[16];
        const int klo2 = t & 3;
        const int m = t >> 2;
        const int base2 = klo2 + 132 * m;  // SADDR(k_lo2 + 128m); +4j exact
#pragma unroll
        for (int q = 0; q < 16; q++) {
            u[q].x = s[base2 + 8 * q];       // j = 2q
            u[q].y = s[base2 + 8 * q + 4];   // j = 2q+1
        }

#pragma unroll
        for (int q = 0; q < 16; q++) bfly_in(u[q]);
        packed_stages(u, 1, 8);

        // write back to the SAME addresses (thread-private this phase)
#pragma unroll
        for (int q = 0; q < 16; q++) {
            s[base2 + 8 * q]     = u[q].x;
            s[base2 + 8 * q + 4] = u[q].y;
        }
    }
    __syncthreads();

    // ================= Phase 3 =================
    // e = k_lo3 + 4*l + 128*km + 1024*w3 ; reg k = 4*km + k_lo3
    // butterfly e-bits {7,8} = reg strides 4,8 = pair strides 2,4
    {
        float2 w[16];
        const int l = t & 31;
        const int w3 = t >> 5;
        const int base3 = 4 * l + 1056 * w3;  // SADDR(4l + 1024*w3)
#pragma unroll
        for (int km = 0; km < 8; km++) {
            float4 f = *reinterpret_cast<const float4*>(&s[base3 + 132 * km]);
            w[2 * km + 0] = make_float2(f.x, f.y);
            w[2 * km + 1] = make_float2(f.z, f.w);
        }

        packed_stages(w, 2, 4);

        // fully coalesced float4 stores (same addressing as R8)
#pragma unroll
        for (int km = 0; km < 8; km++) {
            stg_hint(oq + l + 32 * km + 256 * w3,
                     make_float4(w[2 * km].x, w[2 * km].y,
                                 w[2 * km + 1].x, w[2 * km + 1].y),
                     pol_st);
        }
    }
}

extern "C" void kernel_launch(void* const* d_in, const int* in_sizes, int n_in,
                              void* d_out, int out_size) {
    // x is the input whose element count equals out_size (N_TOKENS*DIM);
    // H is implicit in the transform and never read.
    const float* x = (const float*)d_in[0];
    for (int i = 0; i < n_in; i++) {
        if (in_sizes[i] == out_size) { x = (const float*)d_in[i]; break; }
    }
    float* out = (float*)d_out;
    const int n_rows = out_size / DIM;  // 8192
    fwht4096_v13_kernel<<<n_rows, THREADS>>>(x, out);
}